// round 4
// baseline (speedup 1.0000x reference)
#include <cuda_runtime.h>

// ---------------------------------------------------------------------------
// SynthMorphLoss: soft-dice over 26-class label maps + diffusion regularizer.
// Inputs (metadata order):
//   d_in[0]: fixed_label_map   int32 [1,160,192,224]   (6,881,280)
//   d_in[1]: warped_moving     int32 [1,160,192,224]   (6,881,280)
//   d_in[2]: vector_field      float32 [1,3,160,192,224] (20,643,840)
// Output: float32[3] = (total, similarity, smoothness)
// ---------------------------------------------------------------------------

#define NBINS 26
#define HT 128          // histogram kernel threads/block
#define DT 256          // diffusion kernel threads/block

__device__ unsigned g_hist[3 * NBINS];   // [fixed_vol | moving_vol | intersection]
__device__ double   g_sums[3];           // [sum dz^2, sum dy^2, sum dx^2]

// ---- zero scratch ---------------------------------------------------------
__global__ void zero_k() {
    int t = threadIdx.x;
    if (t < 3 * NBINS) g_hist[t] = 0u;
    if (t < 3)         g_sums[t] = 0.0;
}

// ---- histogram: per-thread private SMEM counters (no atomics in hot loop) -
__global__ __launch_bounds__(HT) void hist_k(const int* __restrict__ f,
                                             const int* __restrict__ m,
                                             int n4) {
    // layout: s[type*NBINS*HT + bin*HT + tid]  -> bank = tid%32, conflict-free
    __shared__ unsigned s[3 * NBINS * HT];
    const int tid = threadIdx.x;
    for (int j = tid; j < 3 * NBINS * HT; j += HT) s[j] = 0u;
    __syncthreads();

    const int4* f4 = (const int4*)f;
    const int4* m4 = (const int4*)m;
    const int step = gridDim.x * HT;
    int i = blockIdx.x * HT + tid;

    auto proc = [&](int fa, int mb) {
        unsigned fu = min((unsigned)fa, 25u);
        unsigned mu = min((unsigned)mb, 25u);
        s[fu * HT + tid] += 1u;
        s[NBINS * HT + mu * HT + tid] += 1u;
        if (fu == mu) s[2 * NBINS * HT + fu * HT + tid] += 1u;
    };

    // 2x unrolled grid-stride: 4 independent LDG.128 in flight per warp
    for (; i + step < n4; i += 2 * step) {
        int4 a0 = f4[i],        b0 = m4[i];
        int4 a1 = f4[i + step], b1 = m4[i + step];
        proc(a0.x, b0.x); proc(a0.y, b0.y); proc(a0.z, b0.z); proc(a0.w, b0.w);
        proc(a1.x, b1.x); proc(a1.y, b1.y); proc(a1.z, b1.z); proc(a1.w, b1.w);
    }
    if (i < n4) {
        int4 a = f4[i], b = m4[i];
        proc(a.x, b.x); proc(a.y, b.y); proc(a.z, b.z); proc(a.w, b.w);
    }
    __syncthreads();

    // block reduce: thread j sums row j (rotated start -> conflict-free)
    for (int j = tid; j < 3 * NBINS; j += HT) {
        unsigned sum = 0;
        const unsigned* p = &s[j * HT];
        #pragma unroll 4
        for (int kk = 0; kk < HT; kk++) {
            int k = (kk + tid) & (HT - 1);
            sum += p[k];
        }
        atomicAdd(&g_hist[j], sum);
    }
}

// ---- diffusion: sum of squared forward differences along z/y/x ------------
__global__ __launch_bounds__(DT) void diff_k(const float* __restrict__ vf, int n4) {
    const float4* v4 = (const float4*)vf;
    const int W4 = 56, H = 192;       // W=224 -> 56 float4/row; D=160
    float sx = 0.f, sy = 0.f, sz = 0.f;
    const int step = gridDim.x * DT;

    for (int i = blockIdx.x * DT + threadIdx.x; i < n4; i += step) {
        float4 v = v4[i];
        unsigned x4 = (unsigned)i % 56u;
        unsigned t  = (unsigned)i / 56u;
        unsigned y  = t % 192u;
        unsigned z  = (t / 192u) % 160u;

        // x-direction: 3 internal diffs + 1 crossing into next float4
        float d0 = v.y - v.x, d1 = v.z - v.y, d2 = v.w - v.z;
        float lx = d0 * d0 + d1 * d1 + d2 * d2;
        if (x4 < 55u) {
            float nx = __ldg(&vf[4 * i + 4]);
            float d = nx - v.w;
            lx += d * d;
        }
        sx += lx;

        if (y < 191u) {                      // y-neighbor: +896B, L1 hit
            float4 u = v4[i + W4];
            float a = u.x - v.x, b = u.y - v.y, c = u.z - v.z, e = u.w - v.w;
            sy += a * a + b * b + c * c + e * e;
        }
        if (z < 159u) {                      // z-neighbor: +172KB, L2 hit
            float4 u = v4[i + W4 * H];
            float a = u.x - v.x, b = u.y - v.y, c = u.z - v.z, e = u.w - v.w;
            sz += a * a + b * b + c * c + e * e;
        }
    }

    // warp reduce
    #pragma unroll
    for (int o = 16; o > 0; o >>= 1) {
        sz += __shfl_down_sync(0xffffffffu, sz, o);
        sy += __shfl_down_sync(0xffffffffu, sy, o);
        sx += __shfl_down_sync(0xffffffffu, sx, o);
    }
    __shared__ float r[3][DT / 32];
    int lane = threadIdx.x & 31, w = threadIdx.x >> 5;
    if (lane == 0) { r[0][w] = sz; r[1][w] = sy; r[2][w] = sx; }
    __syncthreads();
    if (threadIdx.x == 0) {
        float tz = 0.f, ty = 0.f, tx = 0.f;
        #pragma unroll
        for (int k = 0; k < DT / 32; k++) { tz += r[0][k]; ty += r[1][k]; tx += r[2][k]; }
        atomicAdd(&g_sums[0], (double)tz);
        atomicAdd(&g_sums[1], (double)ty);
        atomicAdd(&g_sums[2], (double)tx);
    }
}

// ---- finalize: dice + means -> out[3] -------------------------------------
__global__ void final_k(float* __restrict__ out) {
    if (threadIdx.x != 0) return;
    const double eps = 1e-5;
    double acc = 0.0;
    #pragma unroll
    for (int c = 1; c < 26; c++) {   // class 0 ignored
        double inter = (double)g_hist[2 * NBINS + c];
        double fv    = (double)g_hist[c];
        double mv    = (double)g_hist[NBINS + c];
        acc += (2.0 * inter + eps) / (fv + mv + eps);
    }
    double sim = 1.0 - acc / 25.0;
    // denominators: 3*159*192*224, 3*160*191*224, 3*160*192*223
    double sm = (g_sums[0] / 20514816.0 +
                 g_sums[1] / 20536320.0 +
                 g_sums[2] / 20551680.0) / 3.0;
    out[0] = (float)(sim + sm);
    out[1] = (float)sim;
    out[2] = (float)sm;
}

// ---------------------------------------------------------------------------
extern "C" void kernel_launch(void* const* d_in, const int* in_sizes, int n_in,
                              void* d_out, int out_size) {
    const int*   fixedmap = (const int*)d_in[0];
    const int*   moving   = (const int*)d_in[1];
    const float* vf       = (const float*)d_in[2];
    float*       out      = (float*)d_out;

    int nvox4 = in_sizes[0] / 4;   // 1,720,320 int4
    int nvf4  = in_sizes[2] / 4;   // 5,160,960 float4

    zero_k<<<1, 128>>>();
    hist_k<<<740, HT>>>(fixedmap, moving, nvox4);   // 148 SMs x 5 resident blocks
    diff_k<<<1184, DT>>>(vf, nvf4);
    final_k<<<1, 32>>>(out);
}

// round 5
// speedup vs baseline: 1.3735x; 1.3735x over previous
#include <cuda_runtime.h>

// ---------------------------------------------------------------------------
// SynthMorphLoss fused single-kernel:
//   phase 1: 26-bin histograms of two int32 label maps (packed u8 SMEM ctrs)
//   phase 2: diffusion regularizer (sum of squared forward diffs z/y/x)
//   last block: parallel dice + means -> out[3], then resets scratch.
// Inputs: d_in[0] int32[6881280], d_in[1] int32[6881280],
//         d_in[2] float32[20643840] = [1,3,160,192,224]
// Output: float32[3] = (total, similarity, smoothness)
// ---------------------------------------------------------------------------

#define T     256
#define GRID  1184          // 148 SMs x 8 blocks -> exactly one wave
#define NBINS 26
#define NW    21            // 3 types * ceil(26/4) packed words per thread

__device__ unsigned g_hist[3 * NBINS];  // [fixed_vol | moving_vol | intersection]
__device__ double   g_sums[3];          // [sum dz^2, sum dy^2, sum dx^2]
__device__ unsigned g_done;

__global__ __launch_bounds__(T) void fused_k(const int* __restrict__ f,
                                             const int* __restrict__ m,
                                             const float* __restrict__ vf,
                                             float* __restrict__ out,
                                             int n4lab, int n4vf) {
    // packed per-thread counters: word (type*7 + bin/4), byte lane = bin%4
    __shared__ unsigned s[NW * T];      // 21.5 KB
    __shared__ float    r[3][T / 32];
    __shared__ int      slast;
    const int tid = threadIdx.x;
    const int bid = blockIdx.x;

    #pragma unroll
    for (int w = 0; w < NW; w++) s[w * T + tid] = 0u;
    __syncthreads();

    // ================= phase 1: histogram =================
    {
        const int4* f4 = (const int4*)f;
        const int4* m4 = (const int4*)m;
        const int step = GRID * T;

        auto proc = [&](int fa, int mb) {
            unsigned fu = min((unsigned)fa, 25u);
            unsigned mu = min((unsigned)mb, 25u);
            s[(fu >> 2) * T + tid]        += 1u << ((fu & 3u) * 8u);
            s[(7u + (mu >> 2)) * T + tid] += 1u << ((mu & 3u) * 8u);
            if (fu == mu)
                s[(14u + (fu >> 2)) * T + tid] += 1u << ((fu & 3u) * 8u);
        };

        for (int i = bid * T + tid; i < n4lab; i += step) {
            int4 a = f4[i], b = m4[i];
            proc(a.x, b.x); proc(a.y, b.y); proc(a.z, b.z); proc(a.w, b.w);
        }
        __syncthreads();

        // block reduce: thread j (j<78) owns one (type,bin); rotated scan,
        // bank = (kk+tid)&31 -> conflict-free across the warp
        if (tid < 3 * NBINS) {
            int type = tid / NBINS;
            int c    = tid - type * NBINS;
            const unsigned* p = &s[(type * 7 + (c >> 2)) * T];
            int sh = (c & 3) * 8;
            unsigned sum = 0;
            #pragma unroll 8
            for (int kk = 0; kk < T; kk++) {
                int k = (kk + tid) & (T - 1);
                sum += (p[k] >> sh) & 0xFFu;
            }
            atomicAdd(&g_hist[tid], sum);
            __threadfence();            // order my RED before my barrier arrival
        }
    }

    // ================= phase 2: diffusion =================
    {
        const float4* v4 = (const float4*)vf;
        const int W4 = 56, H = 192;     // W=224 -> 56 float4/row; D=160
        float sx = 0.f, sy = 0.f, sz = 0.f;
        const int step = GRID * T;

        for (int i = bid * T + tid; i < n4vf; i += step) {
            float4 v = v4[i];
            unsigned x4 = (unsigned)i % 56u;
            unsigned t  = (unsigned)i / 56u;
            unsigned y  = t % 192u;
            unsigned z  = (t / 192u) % 160u;

            float d0 = v.y - v.x, d1 = v.z - v.y, d2 = v.w - v.z;
            float lx = d0 * d0 + d1 * d1 + d2 * d2;
            if (x4 < 55u) {
                float nx = __ldg(&vf[4 * i + 4]);
                float d = nx - v.w;
                lx += d * d;
            }
            sx += lx;

            if (y < 191u) {                       // +896 B -> L1 hit
                float4 u = v4[i + W4];
                float a = u.x - v.x, b = u.y - v.y, c = u.z - v.z, e = u.w - v.w;
                sy += a * a + b * b + c * c + e * e;
            }
            if (z < 159u) {                       // +172 KB -> L2 hit
                float4 u = v4[i + W4 * H];
                float a = u.x - v.x, b = u.y - v.y, c = u.z - v.z, e = u.w - v.w;
                sz += a * a + b * b + c * c + e * e;
            }
        }

        #pragma unroll
        for (int o = 16; o > 0; o >>= 1) {
            sz += __shfl_down_sync(0xffffffffu, sz, o);
            sy += __shfl_down_sync(0xffffffffu, sy, o);
            sx += __shfl_down_sync(0xffffffffu, sx, o);
        }
        int lane = tid & 31, w = tid >> 5;
        if (lane == 0) { r[0][w] = sz; r[1][w] = sy; r[2][w] = sx; }
        __syncthreads();
        if (tid == 0) {
            float tz = 0.f, ty = 0.f, tx = 0.f;
            #pragma unroll
            for (int k = 0; k < T / 32; k++) { tz += r[0][k]; ty += r[1][k]; tx += r[2][k]; }
            atomicAdd(&g_sums[0], (double)tz);
            atomicAdd(&g_sums[1], (double)ty);
            atomicAdd(&g_sums[2], (double)tx);
            __threadfence();
        }
    }

    // ================= completion + finalize in last block =================
    __syncthreads();
    if (tid == 0) {
        unsigned prev = atomicAdd(&g_done, 1u);
        slast = (prev == (unsigned)(GRID - 1));
    }
    __syncthreads();
    if (!slast) return;
    __threadfence();                    // acquire: all blocks' REDs visible

    if (tid < 32) {
        volatile unsigned* vh = g_hist;
        volatile double*   vs = g_sums;
        double term = 0.0;
        if (tid >= 1 && tid < 26) {     // class 0 ignored; 25 parallel fp64 divs
            double inter = (double)vh[2 * NBINS + tid];
            double fv    = (double)vh[tid];
            double mv    = (double)vh[NBINS + tid];
            term = (2.0 * inter + 1e-5) / (fv + mv + 1e-5);
        }
        #pragma unroll
        for (int o = 16; o > 0; o >>= 1)
            term += __shfl_down_sync(0xffffffffu, term, o);
        if (tid == 0) {
            double sim = 1.0 - term / 25.0;
            // denominators: 3*159*192*224, 3*160*191*224, 3*160*192*223
            double sm = (vs[0] / 20514816.0 +
                         vs[1] / 20536320.0 +
                         vs[2] / 20551680.0) / 3.0;
            out[0] = (float)(sim + sm);
            out[1] = (float)sim;
            out[2] = (float)sm;
        }
    }
    __syncthreads();                    // reads done before resets
    if (tid < 3 * NBINS) g_hist[tid] = 0u;      // self-clean for next replay
    if (tid >= 96 && tid < 99) g_sums[tid - 96] = 0.0;
    if (tid == 128) g_done = 0u;
}

// ---------------------------------------------------------------------------
extern "C" void kernel_launch(void* const* d_in, const int* in_sizes, int n_in,
                              void* d_out, int out_size) {
    const int*   fixedmap = (const int*)d_in[0];
    const int*   moving   = (const int*)d_in[1];
    const float* vf       = (const float*)d_in[2];
    float*       out      = (float*)d_out;

    int n4lab = in_sizes[0] / 4;   // 1,720,320 int4
    int n4vf  = in_sizes[2] / 4;   // 5,160,960 float4

    fused_k<<<GRID, T>>>(fixedmap, moving, vf, out, n4lab, n4vf);
}